// round 1
// baseline (speedup 1.0000x reference)
#include <cuda_runtime.h>
#include <math.h>

// Problem constants (static per the reference module)
#define BB      4
#define NPER    2000
#define NATOMS  (BB*NPER)
#define NN      11            // n = 0..10 per axis
#define N2R     21            // n2 = -10..10
#define NPAIR   (NN*N2R)      // 231 (n1,n2) pairs, n1 in [0,10]
#define N3      21            // n3 = -10..10
#define NCHUNK  64            // atom-chunk lanes per (b,pair) block
#define RBLKS   38            // ceil(NPAIR*N3 / 128)

#define KSQ_MAX_F   9.8696044010893586f   // (2*pi/DL)^2, rounds to fp32 like JAX
#define TWOPI_F     6.2831854820251465f   // fl32(2*pi)
#define INV_SELF    0.0634936359342410f   // 1/(sigma*(2*pi)^1.5), sigma=1
#define NORM_F      90.0474f
#define EPS_F       1e-6f

// ---------------- device scratch (no allocations allowed) ----------------
__device__ float  g_cinv[BB][3][3];   // inv(cell)
__device__ float  g_vol[BB];          // det(cell)
__device__ float  g_pot[BB];          // reciprocal-space accumulator
__device__ float2 g_tabx[BB][NN][NPER];   // q * e^{i 2pi n s0}  (q premultiplied)
__device__ float2 g_taby[BB][NN][NPER];   //     e^{i 2pi n s1}
__device__ float2 g_tabz[BB][NN][NPER];   //     e^{i 2pi n s2}
__device__ float2 g_part[BB][NPAIR][N3][NCHUNK]; // partial S per chunk

// ---------------- kernel 1: cell inverse, det, zero pot ----------------
__global__ void k_setup(const float* __restrict__ cell) {
    int b = threadIdx.x;
    if (b >= BB) return;
    const float* m = cell + b * 9;
    float m00=m[0], m01=m[1], m02=m[2];
    float m10=m[3], m11=m[4], m12=m[5];
    float m20=m[6], m21=m[7], m22=m[8];
    float c00 = m11*m22 - m12*m21;
    float c01 = m12*m20 - m10*m22;
    float c02 = m10*m21 - m11*m20;
    float det = m00*c00 + m01*c01 + m02*c02;
    float inv = 1.0f / det;
    g_cinv[b][0][0] = c00 * inv;
    g_cinv[b][0][1] = (m02*m21 - m01*m22) * inv;
    g_cinv[b][0][2] = (m01*m12 - m02*m11) * inv;
    g_cinv[b][1][0] = c01 * inv;
    g_cinv[b][1][1] = (m00*m22 - m02*m20) * inv;
    g_cinv[b][1][2] = (m02*m10 - m00*m12) * inv;
    g_cinv[b][2][0] = c02 * inv;
    g_cinv[b][2][1] = (m01*m20 - m00*m21) * inv;
    g_cinv[b][2][2] = (m00*m11 - m01*m10) * inv;
    g_vol[b] = det;
    g_pot[b] = 0.0f;
}

// ---------------- kernel 2: per-atom phase tables ----------------
__global__ void k_tab(const float* __restrict__ q, const float* __restrict__ r) {
    int idx = blockIdx.x * blockDim.x + threadIdx.x;
    if (idx >= NATOMS) return;
    int b = idx / NPER;
    int a = idx - b * NPER;
    float r0 = r[3*idx+0], r1 = r[3*idx+1], r2 = r[3*idx+2];
    float qv = q[idx];
    float s0 = r0*g_cinv[b][0][0] + r1*g_cinv[b][1][0] + r2*g_cinv[b][2][0];
    float s1 = r0*g_cinv[b][0][1] + r1*g_cinv[b][1][1] + r2*g_cinv[b][2][1];
    float s2 = r0*g_cinv[b][0][2] + r1*g_cinv[b][1][2] + r2*g_cinv[b][2][2];
    #pragma unroll
    for (int n = 0; n < NN; n++) {
        float si, co, u, f;
        u = n * s0; f = u - rintf(u);
        sincospif(2.0f * f, &si, &co);
        g_tabx[b][n][a] = make_float2(qv * co, qv * si);
        u = n * s1; f = u - rintf(u);
        sincospif(2.0f * f, &si, &co);
        g_taby[b][n][a] = make_float2(co, si);
        u = n * s2; f = u - rintf(u);
        sincospif(2.0f * f, &si, &co);
        g_tabz[b][n][a] = make_float2(co, si);
    }
}

// ---------------- kernel 3: structure factors, 21 n3 per thread ----------------
__global__ void __launch_bounds__(NCHUNK) k_main() {
    int blk  = blockIdx.x;
    int b    = blk / NPAIR;
    int pair = blk - b * NPAIR;
    int n1   = pair / N2R;
    int n2   = pair % N2R - 10;

    // G[d][e] = 2*pi * cinv[e][d]; skip block if no n3 can be inside the cutoff
    float gm[3][3];
    #pragma unroll
    for (int d = 0; d < 3; d++)
        #pragma unroll
        for (int e = 0; e < 3; e++)
            gm[d][e] = TWOPI_F * g_cinv[b][e][d];
    bool any = false;
    #pragma unroll
    for (int t = 0; t < N3; t++) {
        float n3 = (float)(t - 10);
        float kv0 = n1*gm[0][0] + n2*gm[1][0] + n3*gm[2][0];
        float kv1 = n1*gm[0][1] + n2*gm[1][1] + n3*gm[2][1];
        float kv2 = n1*gm[0][2] + n2*gm[1][2] + n3*gm[2][2];
        float ksq = kv0*kv0 + kv1*kv1 + kv2*kv2;
        any = any || (ksq > 0.0f && ksq <= KSQ_MAX_F * 1.001f);
    }
    if (!any) return;

    int   an2 = n2 < 0 ? -n2 : n2;
    float sgn = n2 < 0 ? -1.0f : 1.0f;
    const float2* __restrict__ tx = &g_tabx[b][n1][0];
    const float2* __restrict__ ty = &g_taby[b][an2][0];
    const float2* __restrict__ tz = &g_tabz[b][0][0];

    float accr[N3], acci[N3];
    #pragma unroll
    for (int j = 0; j < N3; j++) { accr[j] = 0.0f; acci[j] = 0.0f; }

    for (int a = threadIdx.x; a < NPER; a += NCHUNK) {
        float2 X = tx[a];          // q * Ex(n1)
        float2 Y = ty[a];
        float  yy = Y.y * sgn;     // conj for n2 < 0
        float  ar = X.x * Y.x - X.y * yy;
        float  ai = X.x * yy + X.y * Y.x;
        accr[10] += ar;
        acci[10] += ai;
        #pragma unroll
        for (int m = 1; m <= 10; m++) {
            float2 Z = tz[m * NPER + a];
            float p1 = ar * Z.x;
            float p2 = ai * Z.y;
            float p3 = ar * Z.y;
            float p4 = ai * Z.x;
            accr[10+m] += p1 - p2;   // S(+n3)
            acci[10+m] += p3 + p4;
            accr[10-m] += p1 + p2;   // S(-n3) uses conj(Ez)
            acci[10-m] += p4 - p3;
        }
    }
    #pragma unroll
    for (int j = 0; j < N3; j++)
        g_part[b][pair][j][threadIdx.x] = make_float2(accr[j], acci[j]);
}

// ---------------- kernel 4: chunk reduce + k-space weighting ----------------
__global__ void k_reduce() {
    const int ENT = NPAIR * N3;          // 4851
    int b = blockIdx.x / RBLKS;
    int e = (blockIdx.x % RBLKS) * 128 + threadIdx.x;
    float contrib = 0.0f;
    if (e < ENT) {
        int pair = e / N3;
        int n3i  = e - pair * N3;
        int n1   = pair / N2R;
        int n2   = pair % N2R - 10;
        int n3   = n3i - 10;
        float Sx = 0.0f, Sy = 0.0f;
        const float2* __restrict__ p = &g_part[b][pair][n3i][0];
        #pragma unroll 8
        for (int c = 0; c < NCHUNK; c++) { float2 v = p[c]; Sx += v.x; Sy += v.y; }
        float kv0 = n1*(TWOPI_F*g_cinv[0][0][0]) ; // placeholder, recomputed below properly
        // recompute with this batch's cinv (kept simple & fp32 to mirror the reference)
        float g00 = TWOPI_F * g_cinv[b][0][0], g01 = TWOPI_F * g_cinv[b][1][0], g02 = TWOPI_F * g_cinv[b][2][0];
        float g10 = TWOPI_F * g_cinv[b][0][1], g11 = TWOPI_F * g_cinv[b][1][1], g12 = TWOPI_F * g_cinv[b][2][1];
        float g20 = TWOPI_F * g_cinv[b][0][2], g21 = TWOPI_F * g_cinv[b][1][2], g22 = TWOPI_F * g_cinv[b][2][2];
        kv0 = n1*g00 + n2*g01 + n3*g02;
        float kv1 = n1*g10 + n2*g11 + n3*g12;
        float kv2 = n1*g20 + n2*g21 + n3*g22;
        float ksq = kv0*kv0 + kv1*kv1 + kv2*kv2;
        if (ksq > 0.0f && ksq <= KSQ_MAX_F) {
            float w    = (n1 > 0) ? 2.0f : 1.0f;
            float kfac = expf(-0.5f * ksq) / (ksq + EPS_F);
            contrib = w * kfac * (Sx*Sx + Sy*Sy);
        }
    }
    __shared__ float sd[128];
    sd[threadIdx.x] = contrib;
    __syncthreads();
    #pragma unroll
    for (int s = 64; s > 0; s >>= 1) {
        if (threadIdx.x < s) sd[threadIdx.x] += sd[threadIdx.x + s];
        __syncthreads();
    }
    if (threadIdx.x == 0) atomicAdd(&g_pot[b], sd[0]);
}

// ---------------- kernel 5: self energy + final output ----------------
__global__ void k_final(const float* __restrict__ q, float* __restrict__ out) {
    int b = blockIdx.x;
    __shared__ float sd[128];
    float s = 0.0f;
    for (int a = threadIdx.x; a < NPER; a += 128) {
        float qv = q[b * NPER + a];
        s += qv * qv;
    }
    sd[threadIdx.x] = s;
    __syncthreads();
    #pragma unroll
    for (int t = 64; t > 0; t >>= 1) {
        if (threadIdx.x < t) sd[threadIdx.x] += sd[threadIdx.x + t];
        __syncthreads();
    }
    if (threadIdx.x == 0) {
        float pot = g_pot[b] / g_vol[b] - sd[0] * INV_SELF;
        out[b] = pot * NORM_F;
    }
}

// ---------------- launch ----------------
extern "C" void kernel_launch(void* const* d_in, const int* in_sizes, int n_in,
                              void* d_out, int out_size) {
    const float* q    = (const float*)d_in[0];
    const float* r    = (const float*)d_in[1];
    const float* cell = (const float*)d_in[2];
    float* out = (float*)d_out;

    k_setup<<<1, 32>>>(cell);
    k_tab<<<(NATOMS + 127) / 128, 128>>>(q, r);
    k_main<<<BB * NPAIR, NCHUNK>>>();
    k_reduce<<<BB * RBLKS, 128>>>();
    k_final<<<BB, 128>>>(q, out);
}

// round 2
// speedup vs baseline: 1.9637x; 1.9637x over previous
#include <cuda_runtime.h>
#include <math.h>

// Problem constants (static per the reference module)
#define BB      4
#define NPER    2000
#define NATOMS  (BB*NPER)
#define NN      11            // n = 0..10 per axis
#define NM2     11            // |n2| = 0..10
#define N3      21            // n3 = -10..10
#define NT      128           // threads per k_main block

#define KSQ_MAX_F   9.8696044010893586f   // (2*pi/DL)^2 in fp32, as JAX computes
#define TWOPI_F     6.2831854820251465f   // fp32(2*pi)
#define INV_SELF    0.0634936359342410f   // 1/(sigma*(2*pi)^1.5), sigma=1
#define NORM_F      90.0474f
#define EPS_F       1e-6f

// ---------------- device scratch (no allocations allowed) ----------------
__device__ float  g_cinv[BB][3][3];       // inv(cell)
__device__ float  g_vol[BB];              // det(cell)
__device__ float  g_pot[BB];              // reciprocal-space accumulator
__device__ float2 g_tabx[BB][NN][NPER];   // q * e^{i 2pi n s0}  (q premultiplied)
__device__ float2 g_taby[BB][NN][NPER];   //     e^{i 2pi n s1}
__device__ float2 g_tabz[BB][NN][NPER];   //     e^{i 2pi n s2}

// ---------------- kernel 1: phase tables (+ inline cell setup) ----------------
__global__ void k_tab(const float* __restrict__ q, const float* __restrict__ r,
                      const float* __restrict__ cell) {
    int idx = blockIdx.x * blockDim.x + threadIdx.x;
    if (idx >= NATOMS) return;
    int b = idx / NPER;
    int a = idx - b * NPER;

    // local 3x3 inverse (redundant per thread; trivial ALU)
    const float* m = cell + b * 9;
    float m00=m[0], m01=m[1], m02=m[2];
    float m10=m[3], m11=m[4], m12=m[5];
    float m20=m[6], m21=m[7], m22=m[8];
    float c00 = m11*m22 - m12*m21;
    float c01 = m12*m20 - m10*m22;
    float c02 = m10*m21 - m11*m20;
    float det = m00*c00 + m01*c01 + m02*c02;
    float inv = 1.0f / det;
    float i00 = c00 * inv;
    float i01 = (m02*m21 - m01*m22) * inv;
    float i02 = (m01*m12 - m02*m11) * inv;
    float i10 = c01 * inv;
    float i11 = (m00*m22 - m02*m20) * inv;
    float i12 = (m02*m10 - m00*m12) * inv;
    float i20 = c02 * inv;
    float i21 = (m01*m20 - m00*m21) * inv;
    float i22 = (m00*m11 - m01*m10) * inv;

    if (a == 0) {
        g_cinv[b][0][0]=i00; g_cinv[b][0][1]=i01; g_cinv[b][0][2]=i02;
        g_cinv[b][1][0]=i10; g_cinv[b][1][1]=i11; g_cinv[b][1][2]=i12;
        g_cinv[b][2][0]=i20; g_cinv[b][2][1]=i21; g_cinv[b][2][2]=i22;
        g_vol[b] = det;
        g_pot[b] = 0.0f;
    }

    float r0 = r[3*idx+0], r1 = r[3*idx+1], r2 = r[3*idx+2];
    float qv = q[idx];
    float s0 = r0*i00 + r1*i10 + r2*i20;
    float s1 = r0*i01 + r1*i11 + r2*i21;
    float s2 = r0*i02 + r1*i12 + r2*i22;
    #pragma unroll
    for (int n = 0; n < NN; n++) {
        float si, co, u, f;
        u = n * s0; f = u - rintf(u);
        sincospif(2.0f * f, &si, &co);
        g_tabx[b][n][a] = make_float2(qv * co, qv * si);
        u = n * s1; f = u - rintf(u);
        sincospif(2.0f * f, &si, &co);
        g_taby[b][n][a] = make_float2(co, si);
        u = n * s2; f = u - rintf(u);
        sincospif(2.0f * f, &si, &co);
        g_tabz[b][n][a] = make_float2(co, si);
    }
}

// ---------------- kernel 2: structure factors + fused reduction ----------------
// Block = (b, n1, |n2|). Each thread accumulates S for BOTH n2 signs x 21 n3.
__global__ void __launch_bounds__(NT) k_main() {
    int blk = blockIdx.x;
    int b   = blk / (NN * NM2);
    int rem = blk - b * (NN * NM2);
    int n1  = rem / NM2;
    int m2  = rem - n1 * NM2;      // |n2|

    // G rows (fp32, exact order as reference): g{e}{d}? we need kv_e = sum_d n_d * G[d][e]
    float g00 = TWOPI_F * g_cinv[b][0][0], g01 = TWOPI_F * g_cinv[b][1][0], g02 = TWOPI_F * g_cinv[b][2][0];
    float g10 = TWOPI_F * g_cinv[b][0][1], g11 = TWOPI_F * g_cinv[b][1][1], g12 = TWOPI_F * g_cinv[b][2][1];
    float g20 = TWOPI_F * g_cinv[b][0][2], g21 = TWOPI_F * g_cinv[b][1][2], g22 = TWOPI_F * g_cinv[b][2][2];

    // conservative early exit: any (sign, n3) within cutoff?
    bool any = false;
    #pragma unroll
    for (int s = 0; s < 2; s++) {
        float fn2 = s ? -(float)m2 : (float)m2;
        #pragma unroll
        for (int t = 0; t < N3; t++) {
            float n3 = (float)(t - 10);
            float kv0 = n1*g00 + fn2*g01 + n3*g02;
            float kv1 = n1*g10 + fn2*g11 + n3*g12;
            float kv2 = n1*g20 + fn2*g21 + n3*g22;
            float ksq = kv0*kv0 + kv1*kv1 + kv2*kv2;
            any = any || (ksq > 0.0f && ksq <= KSQ_MAX_F * 1.001f);
        }
    }
    if (!any) return;

    const float2* __restrict__ tx = &g_tabx[b][n1][0];
    const float2* __restrict__ ty = &g_taby[b][m2][0];
    const float2* __restrict__ tz = &g_tabz[b][0][0];

    // acc layout: [sign*42 + j*2 + (0=re,1=im)], j = n3+10
    float acc[84];
    #pragma unroll
    for (int j = 0; j < 84; j++) acc[j] = 0.0f;

    for (int a = threadIdx.x; a < NPER; a += NT) {
        float2 X = tx[a];                // q * Ex(n1)
        float2 Y = ty[a];                // Ey(|n2|)
        // sign 0: n2 = +m2 ; sign 1: n2 = -m2 (conj Y)
        float ar0 = X.x*Y.x - X.y*Y.y;
        float ai0 = X.x*Y.y + X.y*Y.x;
        float ar1 = X.x*Y.x + X.y*Y.y;
        float ai1 = X.y*Y.x - X.x*Y.y;
        acc[0*42 + 10*2 + 0] += ar0;  acc[0*42 + 10*2 + 1] += ai0;
        acc[1*42 + 10*2 + 0] += ar1;  acc[1*42 + 10*2 + 1] += ai1;
        #pragma unroll
        for (int m = 1; m <= 10; m++) {
            float2 Z = tz[m * NPER + a];
            // sign 0
            acc[0*42+(10+m)*2+0] = fmaf(ar0, Z.x, fmaf(-ai0, Z.y, acc[0*42+(10+m)*2+0]));
            acc[0*42+(10+m)*2+1] = fmaf(ar0, Z.y, fmaf( ai0, Z.x, acc[0*42+(10+m)*2+1]));
            acc[0*42+(10-m)*2+0] = fmaf(ar0, Z.x, fmaf( ai0, Z.y, acc[0*42+(10-m)*2+0]));
            acc[0*42+(10-m)*2+1] = fmaf(-ar0, Z.y, fmaf(ai0, Z.x, acc[0*42+(10-m)*2+1]));
            // sign 1
            acc[1*42+(10+m)*2+0] = fmaf(ar1, Z.x, fmaf(-ai1, Z.y, acc[1*42+(10+m)*2+0]));
            acc[1*42+(10+m)*2+1] = fmaf(ar1, Z.y, fmaf( ai1, Z.x, acc[1*42+(10+m)*2+1]));
            acc[1*42+(10-m)*2+0] = fmaf(ar1, Z.x, fmaf( ai1, Z.y, acc[1*42+(10-m)*2+0]));
            acc[1*42+(10-m)*2+1] = fmaf(-ar1, Z.y, fmaf(ai1, Z.x, acc[1*42+(10-m)*2+1]));
        }
    }

    // ---- fused reduction ----
    __shared__ float red[4][84];
    __shared__ float cont[48];
    int wid  = threadIdx.x >> 5;
    int lane = threadIdx.x & 31;
    #pragma unroll
    for (int j = 0; j < 84; j++) {
        float v = acc[j];
        v += __shfl_xor_sync(0xffffffffu, v, 16);
        v += __shfl_xor_sync(0xffffffffu, v, 8);
        v += __shfl_xor_sync(0xffffffffu, v, 4);
        v += __shfl_xor_sync(0xffffffffu, v, 2);
        v += __shfl_xor_sync(0xffffffffu, v, 1);
        if (lane == 0) red[wid][j] = v;
    }
    __syncthreads();

    if (threadIdx.x < 48) cont[threadIdx.x] = 0.0f;
    __syncthreads();

    if (threadIdx.x < 42) {
        int sgn = threadIdx.x / 21;         // 0: +m2, 1: -m2
        int j   = threadIdx.x - sgn * 21;   // n3 index
        float c = 0.0f;
        if (!(m2 == 0 && sgn == 1)) {       // avoid double counting n2=0
            int ir = sgn*42 + j*2;
            float Sr = red[0][ir]   + red[1][ir]   + red[2][ir]   + red[3][ir];
            float Si = red[0][ir+1] + red[1][ir+1] + red[2][ir+1] + red[3][ir+1];
            float fn2 = sgn ? -(float)m2 : (float)m2;
            float n3  = (float)(j - 10);
            float kv0 = n1*g00 + fn2*g01 + n3*g02;
            float kv1 = n1*g10 + fn2*g11 + n3*g12;
            float kv2 = n1*g20 + fn2*g21 + n3*g22;
            float ksq = kv0*kv0 + kv1*kv1 + kv2*kv2;
            if (ksq > 0.0f && ksq <= KSQ_MAX_F) {
                float w    = (n1 > 0) ? 2.0f : 1.0f;
                float kfac = expf(-0.5f * ksq) / (ksq + EPS_F);
                c = w * kfac * (Sr*Sr + Si*Si);
            }
        }
        cont[threadIdx.x] = c;
    }
    __syncthreads();
    if (threadIdx.x == 0) {
        float s = 0.0f;
        #pragma unroll
        for (int i = 0; i < 42; i++) s += cont[i];
        atomicAdd(&g_pot[b], s);
    }
}

// ---------------- kernel 3: self energy + final output ----------------
__global__ void k_final(const float* __restrict__ q, float* __restrict__ out) {
    int b = blockIdx.x;
    __shared__ float sd[128];
    float s = 0.0f;
    for (int a = threadIdx.x; a < NPER; a += 128) {
        float qv = q[b * NPER + a];
        s += qv * qv;
    }
    sd[threadIdx.x] = s;
    __syncthreads();
    #pragma unroll
    for (int t = 64; t > 0; t >>= 1) {
        if (threadIdx.x < t) sd[threadIdx.x] += sd[threadIdx.x + t];
        __syncthreads();
    }
    if (threadIdx.x == 0) {
        float pot = g_pot[b] / g_vol[b] - sd[0] * INV_SELF;
        out[b] = pot * NORM_F;
    }
}

// ---------------- launch ----------------
extern "C" void kernel_launch(void* const* d_in, const int* in_sizes, int n_in,
                              void* d_out, int out_size) {
    const float* q    = (const float*)d_in[0];
    const float* r    = (const float*)d_in[1];
    const float* cell = (const float*)d_in[2];
    float* out = (float*)d_out;

    k_tab<<<(NATOMS + 127) / 128, 128>>>(q, r, cell);
    k_main<<<BB * NN * NM2, NT>>>();
    k_final<<<BB, 128>>>(q, out);
}